// round 5
// baseline (speedup 1.0000x reference)
#include <cuda_runtime.h>
#include <cuda_bf16.h>

// SiLU: out = x * sigmoid(x), 4*4096*4096 fp32. Pure HBM stream.
// R3: 8x float4 per thread (MLP=8, 128 B/thread), 32-bit indexing, streaming hints.

constexpr int THREADS = 256;
constexpr int UNROLL  = 8;                       // float4s per thread
constexpr int TILE    = THREADS * UNROLL;        // float4s per block (2048)

__device__ __forceinline__ float silu_f(float x) {
    return x * (1.0f / (1.0f + __expf(-x)));
}

__device__ __forceinline__ float4 silu_v(float4 v) {
    float4 r;
    r.x = silu_f(v.x);
    r.y = silu_f(v.y);
    r.z = silu_f(v.z);
    r.w = silu_f(v.w);
    return r;
}

__global__ void __launch_bounds__(THREADS) silu_vec4_mlp8_kernel(
    const float4* __restrict__ in, float4* __restrict__ out, int n4)
{
    int base = blockIdx.x * TILE + threadIdx.x;

    if (base + (UNROLL - 1) * THREADS < n4) {
        // Fast path: front-batch all 8 loads -> 8 outstanding LDG.128 per thread.
        float4 v[UNROLL];
#pragma unroll
        for (int k = 0; k < UNROLL; k++)
            v[k] = __ldcs(&in[base + k * THREADS]);
#pragma unroll
        for (int k = 0; k < UNROLL; k++)
            __stcs(&out[base + k * THREADS], silu_v(v[k]));
    } else {
        // Edge tile
#pragma unroll
        for (int k = 0; k < UNROLL; k++) {
            int i = base + k * THREADS;
            if (i < n4) __stcs(&out[i], silu_v(__ldcs(&in[i])));
        }
    }
}

__global__ void silu_tail_kernel(
    const float* __restrict__ in, float* __restrict__ out, int start, int n)
{
    int i = start + blockIdx.x * blockDim.x + threadIdx.x;
    if (i < n) out[i] = silu_f(in[i]);
}

extern "C" void kernel_launch(void* const* d_in, const int* in_sizes, int n_in,
                              void* d_out, int out_size) {
    const float* x = (const float*)d_in[0];
    float* out = (float*)d_out;
    int n = in_sizes[0];                 // 67,108,864

    int n4 = n / 4;                      // 16,777,216
    int blocks = (n4 + TILE - 1) / TILE; // 8,192

    silu_vec4_mlp8_kernel<<<blocks, THREADS>>>(
        (const float4*)x, (float4*)out, n4);

    int rem = n - n4 * 4;
    if (rem > 0) {
        int tb = (rem + 255) / 256;
        silu_tail_kernel<<<tb, 256>>>(x, out, n4 * 4, n);
    }
}

// round 8
// speedup vs baseline: 1.0008x; 1.0008x over previous
#include <cuda_runtime.h>
#include <cuda_bf16.h>

// SiLU: out = x * sigmoid(x), 4*4096*4096 fp32. Pure HBM stream.
// R6: UNROLL=4 (best config), branch-free exact-tile kernel when n4 % TILE == 0.
// At 7.17 TB/s effective (~90% of HBM spec) this is at the memory ceiling.

constexpr int THREADS = 256;
constexpr int UNROLL  = 4;                       // float4s per thread
constexpr int TILE    = THREADS * UNROLL;        // 1024 float4s per block

__device__ __forceinline__ float silu_f(float x) {
    return x * (1.0f / (1.0f + __expf(-x)));
}

__device__ __forceinline__ float4 silu_v(float4 v) {
    float4 r;
    r.x = silu_f(v.x);
    r.y = silu_f(v.y);
    r.z = silu_f(v.z);
    r.w = silu_f(v.w);
    return r;
}

// Exact-tiling path: no bounds checks, no branches. Front-batched loads (MLP=4).
__global__ void __launch_bounds__(THREADS) silu_vec4_exact_kernel(
    const float4* __restrict__ in, float4* __restrict__ out)
{
    int base = blockIdx.x * TILE + threadIdx.x;
    float4 v[UNROLL];
#pragma unroll
    for (int k = 0; k < UNROLL; k++)
        v[k] = __ldcs(&in[base + k * THREADS]);
#pragma unroll
    for (int k = 0; k < UNROLL; k++)
        __stcs(&out[base + k * THREADS], silu_v(v[k]));
}

// Generic fallback (any n4).
__global__ void __launch_bounds__(THREADS) silu_vec4_guard_kernel(
    const float4* __restrict__ in, float4* __restrict__ out, int n4)
{
    int base = blockIdx.x * TILE + threadIdx.x;
    if (base + (UNROLL - 1) * THREADS < n4) {
        float4 v[UNROLL];
#pragma unroll
        for (int k = 0; k < UNROLL; k++)
            v[k] = __ldcs(&in[base + k * THREADS]);
#pragma unroll
        for (int k = 0; k < UNROLL; k++)
            __stcs(&out[base + k * THREADS], silu_v(v[k]));
    } else {
#pragma unroll
        for (int k = 0; k < UNROLL; k++) {
            int i = base + k * THREADS;
            if (i < n4) __stcs(&out[i], silu_v(__ldcs(&in[i])));
        }
    }
}

__global__ void silu_tail_kernel(
    const float* __restrict__ in, float* __restrict__ out, int start, int n)
{
    int i = start + blockIdx.x * blockDim.x + threadIdx.x;
    if (i < n) out[i] = silu_f(in[i]);
}

extern "C" void kernel_launch(void* const* d_in, const int* in_sizes, int n_in,
                              void* d_out, int out_size) {
    const float* x = (const float*)d_in[0];
    float* out = (float*)d_out;
    int n = in_sizes[0];                 // 67,108,864

    int n4 = n / 4;                      // 16,777,216 = 16384 * TILE exactly
    if (n4 % TILE == 0) {
        silu_vec4_exact_kernel<<<n4 / TILE, THREADS>>>(
            (const float4*)x, (float4*)out);
    } else {
        int blocks = (n4 + TILE - 1) / TILE;
        silu_vec4_guard_kernel<<<blocks, THREADS>>>(
            (const float4*)x, (float4*)out, n4);
    }

    int rem = n - n4 * 4;
    if (rem > 0) {
        int tb = (rem + 255) / 256;
        silu_tail_kernel<<<tb, 256>>>(x, out, n4 * 4, n);
    }
}